// round 5
// baseline (speedup 1.0000x reference)
#include <cuda_runtime.h>
#include <cuda_bf16.h>

#define NLEV 4
#define MAXS 792
#define NTHREADS 256

// R4: 2 samples/thread -> vectorized loads (int2 / float4), 2x MLP in bytes,
// half the LDG count. Same 464 MB total traffic; goal is pushing DRAM% 60->75.
__global__ __launch_bounds__(NTHREADS) void heal_encoding_kernel2(
    const float2* __restrict__ params2,      // [NLEV*MAXS] as float2
    const float*  __restrict__ pixel_ll,     // [NLEV, B, 2] floats
    const float*  __restrict__ neigh_ll,     // [NLEV, 8, B, 2] floats
    const int*    __restrict__ pixel_idx,    // [NLEV, B]
    const int*    __restrict__ neigh_idx,    // [NLEV, 8, B]
    float*        __restrict__ out,          // [B, 8]  out[b, 4f+l]
    int B)
{
    __shared__ float2 sp[NLEV * MAXS];
    for (int i = threadIdx.x; i < NLEV * MAXS; i += NTHREADS)
        sp[i] = params2[i];
    __syncthreads();

    const int t  = blockIdx.x * NTHREADS + threadIdx.x;
    const int b0 = t * 2;
    if (b0 >= B) return;

    if (b0 + 1 < B) {
        // paired path: all loads vectorized
        float a0[NLEV], a1[NLEV];   // sample b0: f=0, f=1 per level
        float c0[NLEV], c1[NLEV];   // sample b0+1

#pragma unroll
        for (int l = 0; l < NLEV; l++) {
            const int2   pp  = *reinterpret_cast<const int2*>(pixel_idx + l * B + b0);
            const float4 pll = *reinterpret_cast<const float4*>(pixel_ll + (size_t)(l * B + b0) * 2);
            const float2 rA = sp[l * MAXS + pp.x];
            const float2 rB = sp[l * MAXS + pp.y];
            float sA0 = rA.x, sA1 = rA.y;
            float sB0 = rB.x, sB1 = rB.y;
#pragma unroll
            for (int j = 0; j < 8; j++) {
                const size_t base = (size_t)(l * 8 + j) * B + b0;
                const int2   nn  = *reinterpret_cast<const int2*>(neigh_idx + base);
                const float4 nll = *reinterpret_cast<const float4*>(neigh_ll + base * 2);
                if (nn.x >= 0) {
                    const float dx = nll.y - pll.y;      // phi diff, sample A
                    const float dt = nll.x - pll.x;      // theta diff
                    const float w  = rsqrtf(fmaf(dx, dx, dt * dt));
                    const float2 v = sp[l * MAXS + nn.x];
                    sA0 = fmaf(w, v.x, sA0);
                    sA1 = fmaf(w, v.y, sA1);
                }
                if (nn.y >= 0) {
                    const float dx = nll.w - pll.w;      // sample B
                    const float dt = nll.z - pll.z;
                    const float w  = rsqrtf(fmaf(dx, dx, dt * dt));
                    const float2 v = sp[l * MAXS + nn.y];
                    sB0 = fmaf(w, v.x, sB0);
                    sB1 = fmaf(w, v.y, sB1);
                }
            }
            a0[l] = sA0; a1[l] = sA1;
            c0[l] = sB0; c1[l] = sB1;
        }

        float4* op = reinterpret_cast<float4*>(out + (size_t)b0 * 8);
        op[0] = make_float4(a0[0], a0[1], a0[2], a0[3]);
        op[1] = make_float4(a1[0], a1[1], a1[2], a1[3]);
        op[2] = make_float4(c0[0], c0[1], c0[2], c0[3]);
        op[3] = make_float4(c1[0], c1[1], c1[2], c1[3]);
    } else {
        // scalar tail (odd B)
        const int b = b0;
        float acc0[NLEV], acc1[NLEV];
#pragma unroll
        for (int l = 0; l < NLEV; l++) {
            const int    p  = pixel_idx[l * B + b];
            const float2 pl = *reinterpret_cast<const float2*>(pixel_ll + (size_t)(l * B + b) * 2);
            const float2 r  = sp[l * MAXS + p];
            float s0 = r.x, s1 = r.y;
#pragma unroll
            for (int j = 0; j < 8; j++) {
                const size_t base = (size_t)(l * 8 + j) * B + b;
                const int    n  = neigh_idx[base];
                const float2 nl = *reinterpret_cast<const float2*>(neigh_ll + base * 2);
                if (n >= 0) {
                    const float dx = nl.y - pl.y;
                    const float dt = nl.x - pl.x;
                    const float w  = rsqrtf(fmaf(dx, dx, dt * dt));
                    const float2 v = sp[l * MAXS + n];
                    s0 = fmaf(w, v.x, s0);
                    s1 = fmaf(w, v.y, s1);
                }
            }
            acc0[l] = s0; acc1[l] = s1;
        }
        float4* op = reinterpret_cast<float4*>(out + (size_t)b * 8);
        op[0] = make_float4(acc0[0], acc0[1], acc0[2], acc0[3]);
        op[1] = make_float4(acc1[0], acc1[1], acc1[2], acc1[3]);
    }
}

extern "C" void kernel_launch(void* const* d_in, const int* in_sizes, int n_in,
                              void* d_out, int out_size)
{
    // metadata order: params, pixel_latlon, neigh_latlon, pixel_index, neigh_index
    const float2* params2   = (const float2*)d_in[0];
    const float*  pixel_ll  = (const float*)d_in[1];
    const float*  neigh_ll  = (const float*)d_in[2];
    const int*    pixel_idx = (const int*)d_in[3];
    const int*    neigh_idx = (const int*)d_in[4];
    float*        out       = (float*)d_out;

    const int B = in_sizes[3] / NLEV;   // pixel_index has NLEV*B elements

    const int pairs = (B + 1) / 2;
    const int grid  = (pairs + NTHREADS - 1) / NTHREADS;
    heal_encoding_kernel2<<<grid, NTHREADS>>>(
        params2, pixel_ll, neigh_ll, pixel_idx, neigh_idx, out, B);
}

// round 6
// speedup vs baseline: 1.1183x; 1.1183x over previous
#include <cuda_runtime.h>
#include <cuda_bf16.h>

#define NLEV 4
#define MAXS 792
#define NTHREADS 256

// R5: 1 sample/thread; load-first batching (all 17 global loads of a level issued
// back-to-back, no control flow between them) + branchless mask so ptxas can
// front-batch LDGs. __ldcs on streaming read-once data.
__global__ __launch_bounds__(NTHREADS) void heal_encoding_kernel3(
    const float2* __restrict__ params2,      // [NLEV*MAXS] as float2
    const float2* __restrict__ pixel_ll,     // [NLEV, B]
    const float2* __restrict__ neigh_ll,     // [NLEV, 8, B]
    const int*    __restrict__ pixel_idx,    // [NLEV, B]
    const int*    __restrict__ neigh_idx,    // [NLEV, 8, B]
    float*        __restrict__ out,          // [B, 8]  out[b, 4f+l]
    int B)
{
    __shared__ float2 sp[NLEV * MAXS];
    for (int i = threadIdx.x; i < NLEV * MAXS; i += NTHREADS)
        sp[i] = params2[i];
    __syncthreads();

    const int b = blockIdx.x * NTHREADS + threadIdx.x;
    if (b >= B) return;

    float acc0[NLEV];
    float acc1[NLEV];

#pragma unroll
    for (int l = 0; l < NLEV; l++) {
        // ---- batched load phase: 8 idx + 8 latlon + pixel idx + pixel latlon,
        //      all unconditional, no intervening compute ----
        int    nidx[8];
        float2 nll[8];
#pragma unroll
        for (int j = 0; j < 8; j++)
            nidx[j] = __ldcs(neigh_idx + (size_t)(l * 8 + j) * B + b);
#pragma unroll
        for (int j = 0; j < 8; j++)
            nll[j] = __ldcs(neigh_ll + (size_t)(l * 8 + j) * B + b);
        const int    p  = __ldcs(pixel_idx + (size_t)l * B + b);
        const float2 pl = __ldcs(pixel_ll + (size_t)l * B + b);

        // ---- compute phase ----
        const float2 r = sp[l * MAXS + p];   // residual (my_reps)
        float s0 = r.x;
        float s1 = r.y;
#pragma unroll
        for (int j = 0; j < 8; j++) {
            const float dphi = nll[j].y - pl.y;
            const float dth  = nll[j].x - pl.x;
            float w = rsqrtf(fmaf(dphi, dphi, dth * dth));   // 1/d
            w = (nidx[j] >= 0) ? w : 0.0f;                   // masked -> exact 0
            const int gi = nidx[j] >= 0 ? nidx[j] : 0;
            const float2 v = sp[l * MAXS + gi];
            s0 = fmaf(w, v.x, s0);
            s1 = fmaf(w, v.y, s1);
        }
        acc0[l] = s0;
        acc1[l] = s1;
    }

    // out[b, 4f + l]: 8 contiguous floats -> two float4 stores
    float4* op = reinterpret_cast<float4*>(out + (size_t)b * 8);
    op[0] = make_float4(acc0[0], acc0[1], acc0[2], acc0[3]);
    op[1] = make_float4(acc1[0], acc1[1], acc1[2], acc1[3]);
}

extern "C" void kernel_launch(void* const* d_in, const int* in_sizes, int n_in,
                              void* d_out, int out_size)
{
    // metadata order: params, pixel_latlon, neigh_latlon, pixel_index, neigh_index
    const float2* params2   = (const float2*)d_in[0];
    const float2* pixel_ll  = (const float2*)d_in[1];
    const float2* neigh_ll  = (const float2*)d_in[2];
    const int*    pixel_idx = (const int*)d_in[3];
    const int*    neigh_idx = (const int*)d_in[4];
    float*        out       = (float*)d_out;

    const int B = in_sizes[3] / NLEV;   // pixel_index has NLEV*B elements

    const int grid = (B + NTHREADS - 1) / NTHREADS;
    heal_encoding_kernel3<<<grid, NTHREADS>>>(
        params2, pixel_ll, neigh_ll, pixel_idx, neigh_idx, out, B);
}

// round 7
// speedup vs baseline: 1.2353x; 1.1046x over previous
#include <cuda_runtime.h>
#include <cuda_bf16.h>
#include <cstdint>

#define NLEV 4
#define MAXS 792
#define TILE 256

// Packed table: level sizes 36/72/216/792 -> offsets 0/36/108/324, total 1116 float2 (8.9KB)
#define T_OFF0 0
#define T_OFF1 36
#define T_OFF2 108
#define T_OFF3 324
#define T_TOT  1116

struct alignas(16) Stage {
    float2 nll[8][TILE];   // 16 KB
    int    nidx[8][TILE];  //  8 KB
    float2 pll[TILE];      //  2 KB
    int    pidx[TILE];     //  1 KB
};                          // 27648 B

struct alignas(16) Smem {
    Stage  stage[2];        // 55296 B
    float2 tab[T_TOT];      //  8928 B
};                          // 64224 B total

__device__ __forceinline__ void cp16(void* dst_smem, const void* src_gmem) {
    uint32_t d = (uint32_t)__cvta_generic_to_shared(dst_smem);
    asm volatile("cp.async.cg.shared.global [%0], [%1], 16;\n" :: "r"(d), "l"(src_gmem));
}
__device__ __forceinline__ void cp_commit() { asm volatile("cp.async.commit_group;\n" ::: "memory"); }
template <int N> __device__ __forceinline__ void cp_wait() {
    asm volatile("cp.async.wait_group %0;\n" :: "n"(N) : "memory");
}

// Copy one level's 27KB tile (256 samples) into a stage: 1728 x 16B chunks.
__device__ __forceinline__ void copy_level(
    Stage* st, int l, int b0,
    const float2* __restrict__ neigh_ll, const int* __restrict__ neigh_idx,
    const float2* __restrict__ pixel_ll, const int* __restrict__ pixel_idx,
    int B, int tid)
{
    for (int i = tid; i < 1728; i += TILE) {
        if (i < 1024) {                       // nll: 8 rows x 128 chunks
            int row = i >> 7, k = i & 127;
            cp16(&st->nll[row][k * 2], neigh_ll + (size_t)(l * 8 + row) * B + b0 + k * 2);
        } else if (i < 1536) {                // nidx: 8 rows x 64 chunks
            int i2 = i - 1024; int row = i2 >> 6, k = i2 & 63;
            cp16(&st->nidx[row][k * 4], neigh_idx + (size_t)(l * 8 + row) * B + b0 + k * 4);
        } else if (i < 1664) {                // pll: 128 chunks
            int k = i - 1536;
            cp16(&st->pll[k * 2], pixel_ll + (size_t)l * B + b0 + k * 2);
        } else {                              // pidx: 64 chunks
            int k = i - 1664;
            cp16(&st->pidx[k * 4], pixel_idx + (size_t)l * B + b0 + k * 4);
        }
    }
}

__global__ __launch_bounds__(TILE) void heal_encoding_pipe(
    const float2* __restrict__ params2,      // [NLEV, MAXS] float2
    const float2* __restrict__ pixel_ll,     // [NLEV, B]
    const float2* __restrict__ neigh_ll,     // [NLEV, 8, B]
    const int*    __restrict__ pixel_idx,    // [NLEV, B]
    const int*    __restrict__ neigh_idx,    // [NLEV, 8, B]
    float*        __restrict__ out,          // [B, 8]  out[b, 4f+l]
    int B)
{
    extern __shared__ char smem_raw[];
    Smem& s = *reinterpret_cast<Smem*>(smem_raw);
    const int tid = threadIdx.x;
    const int b0  = blockIdx.x * TILE;
    const bool full = (b0 + TILE <= B) && ((B & 3) == 0);
    const int toff[NLEV] = {T_OFF0, T_OFF1, T_OFF2, T_OFF3};

    if (full) {
        // start streaming level 0 immediately
        copy_level(&s.stage[0], 0, b0, neigh_ll, neigh_idx, pixel_ll, pixel_idx, B, tid);
        cp_commit();
    }

    // packed param table (levels 36/72/216/792 of the padded 792 rows)
    {
        const int tsz[NLEV] = {36, 72, 216, 792};
#pragma unroll
        for (int l = 0; l < NLEV; l++)
            for (int i = tid; i < tsz[l]; i += TILE)
                s.tab[toff[l] + i] = params2[l * MAXS + i];
    }
    __syncthreads();

    if (full) {
        float acc0[NLEV], acc1[NLEV];
#pragma unroll
        for (int l = 0; l < NLEV; l++) {
            if (l + 1 < NLEV) {
                copy_level(&s.stage[(l + 1) & 1], l + 1, b0,
                           neigh_ll, neigh_idx, pixel_ll, pixel_idx, B, tid);
                cp_commit();
                cp_wait<1>();            // level l's copy complete
            } else {
                cp_wait<0>();
            }
            __syncthreads();

            Stage* st = &s.stage[l & 1];
            const float2 pl = st->pll[tid];
            const int    p  = st->pidx[tid];
            const float2 r  = s.tab[toff[l] + p];
            float s0 = r.x, s1 = r.y;
#pragma unroll
            for (int j = 0; j < 8; j++) {
                const int    n  = st->nidx[j][tid];
                const float2 ll = st->nll[j][tid];
                const float dphi = ll.y - pl.y;
                const float dth  = ll.x - pl.x;
                float w = rsqrtf(fmaf(dphi, dphi, dth * dth));
                w = (n >= 0) ? w : 0.0f;
                const float2 v = s.tab[toff[l] + (n >= 0 ? n : 0)];
                s0 = fmaf(w, v.x, s0);
                s1 = fmaf(w, v.y, s1);
            }
            acc0[l] = s0; acc1[l] = s1;
            __syncthreads();             // stage (l&1) may be overwritten next iter
        }

        const int b = b0 + tid;
        float4* op = reinterpret_cast<float4*>(out + (size_t)b * 8);
        op[0] = make_float4(acc0[0], acc0[1], acc0[2], acc0[3]);
        op[1] = make_float4(acc1[0], acc1[1], acc1[2], acc1[3]);
    } else {
        // tail / odd-B fallback: direct-LDG path (R5 style), table already in smem
        const int b = b0 + tid;
        if (b < B) {
            float acc0[NLEV], acc1[NLEV];
#pragma unroll
            for (int l = 0; l < NLEV; l++) {
                int    nidx[8];
                float2 nll[8];
#pragma unroll
                for (int j = 0; j < 8; j++)
                    nidx[j] = __ldcs(neigh_idx + (size_t)(l * 8 + j) * B + b);
#pragma unroll
                for (int j = 0; j < 8; j++)
                    nll[j] = __ldcs(neigh_ll + (size_t)(l * 8 + j) * B + b);
                const int    p  = __ldcs(pixel_idx + (size_t)l * B + b);
                const float2 pl = __ldcs(pixel_ll + (size_t)l * B + b);
                const float2 r  = s.tab[toff[l] + p];
                float s0 = r.x, s1 = r.y;
#pragma unroll
                for (int j = 0; j < 8; j++) {
                    const float dphi = nll[j].y - pl.y;
                    const float dth  = nll[j].x - pl.x;
                    float w = rsqrtf(fmaf(dphi, dphi, dth * dth));
                    w = (nidx[j] >= 0) ? w : 0.0f;
                    const float2 v = s.tab[toff[l] + (nidx[j] >= 0 ? nidx[j] : 0)];
                    s0 = fmaf(w, v.x, s0);
                    s1 = fmaf(w, v.y, s1);
                }
                acc0[l] = s0; acc1[l] = s1;
            }
            float4* op = reinterpret_cast<float4*>(out + (size_t)b * 8);
            op[0] = make_float4(acc0[0], acc0[1], acc0[2], acc0[3]);
            op[1] = make_float4(acc1[0], acc1[1], acc1[2], acc1[3]);
        }
    }
}

extern "C" void kernel_launch(void* const* d_in, const int* in_sizes, int n_in,
                              void* d_out, int out_size)
{
    // metadata order: params, pixel_latlon, neigh_latlon, pixel_index, neigh_index
    const float2* params2   = (const float2*)d_in[0];
    const float2* pixel_ll  = (const float2*)d_in[1];
    const float2* neigh_ll  = (const float2*)d_in[2];
    const int*    pixel_idx = (const int*)d_in[3];
    const int*    neigh_idx = (const int*)d_in[4];
    float*        out       = (float*)d_out;

    const int B = in_sizes[3] / NLEV;   // pixel_index has NLEV*B elements

    static_assert(sizeof(Smem) == 64224, "smem layout");
    cudaFuncSetAttribute(heal_encoding_pipe,
                         cudaFuncAttributeMaxDynamicSharedMemorySize, sizeof(Smem));

    const int grid = (B + TILE - 1) / TILE;
    heal_encoding_pipe<<<grid, TILE, sizeof(Smem)>>>(
        params2, pixel_ll, neigh_ll, pixel_idx, neigh_idx, out, B);
}